// round 15
// baseline (speedup 1.0000x reference)
#include <cuda_runtime.h>

// ContourChamferLoss on GB300 (sm_103a) — round 14
// ONE fused kernel: scatter -> software grid barrier -> 8-threads-per-query
// exact NN (float4 candidate loads) -> deterministic reduction.

#define NP_TOT 64000
#define NR_TOT 80000
#define NP     8000
#define NR     10000
#define NTOT   (NP + NR)

// exact f32 replication of jnp.linspace(0, n-1, n//8) index math
#define DELTA_P ((float)(NP_TOT - 1) / (float)(NP - 1))
#define DELTA_R ((float)(NR_TOT - 1) / (float)(NR - 1))

#define GK    32
#define NCELL (GK * GK)
#define CS    (1.0f / (float)GK)
#define CAP   128

#define TPB   128
#define QPB   (TPB / 8)                  // 16 queries per block (8 threads/query)
#define NBLK  ((NTOT + QPB - 1) / QPB)   // 1125 blocks (co-resident: <=8/SM)

#define FULLM 0xFFFFFFFFu

// ---- device scratch (static zero-init; no allocation) ----
// Counters reset by last block each run -> graph replays start clean.
// Bucket slot order may vary, but min is order-independent and partial sums
// are keyed by query index -> bit-stable output.
__device__ int    g_cntP[NCELL];
__device__ int    g_cntR[NCELL];
__device__ float2 g_ptsP[NCELL * CAP];
__device__ float2 g_ptsR[NCELL * CAP];
__device__ float  g_part[NBLK];
__device__ unsigned int g_sync1;         // scatter-done barrier
__device__ unsigned int g_sync2;         // search-done ticket

__device__ __forceinline__ int clamp_cell(int c) {
    return c < 0 ? 0 : (c > GK - 1 ? GK - 1 : c);
}

__device__ __forceinline__ void scan_cell_g(const float2* __restrict__ pts,
                                            const int* __restrict__ cnt,
                                            int c, float px, float py, float& dmin) {
    int m = cnt[c];
    m = m < CAP ? m : CAP;
    const float2* q = pts + c * CAP;
    for (int t = 0; t < m; t++) {
        float2 pp = q[t];
        float ddx = px - pp.x, ddy = py - pp.y;
        dmin = fminf(dmin, fmaf(ddx, ddx, ddy * ddy));
    }
}

__global__ __launch_bounds__(TPB) void chamfer_fused(const float* __restrict__ pc,
                                                     const float* __restrict__ ref,
                                                     float* __restrict__ out) {
    int tid = threadIdx.x;
    int b   = blockIdx.x;

    // ================= phase 1: scatter (first 141 blocks carry points) ======
    int g = b * TPB + tid;
    if (g < NP) {
        int i = (int)((float)g * DELTA_P);
        float2 p = *reinterpret_cast<const float2*>(pc + 2 * i);
        int c = clamp_cell((int)(p.y * (float)GK)) * GK + clamp_cell((int)(p.x * (float)GK));
        int s = atomicAdd(&g_cntP[c], 1);
        if (s < CAP) g_ptsP[c * CAP + s] = p;
    } else if (g < NTOT) {
        int j = g - NP;
        int i = (int)((float)j * DELTA_R);
        float2 p = *reinterpret_cast<const float2*>(ref + 2 * i);
        int c = clamp_cell((int)(p.y * (float)GK)) * GK + clamp_cell((int)(p.x * (float)GK));
        int s = atomicAdd(&g_cntR[c], 1);
        if (s < CAP) g_ptsR[c * CAP + s] = p;
    }

    // ================= software grid barrier (all blocks co-resident) ========
    __syncthreads();
    if (tid == 0) {
        __threadfence();                               // release scatter writes
        atomicAdd(&g_sync1, 1u);
        unsigned int v;
        do {
            asm volatile("ld.acquire.gpu.u32 %0, [%1];"
                         : "=r"(v) : "l"(&g_sync1) : "memory");
            if (v < NBLK) __nanosleep(64);
        } while (v < NBLK);
    }
    __syncthreads();

    // ================= phase 2: search (8 threads per query) =================
    int q   = (b * TPB + tid) >> 3;
    int par = tid & 7;
    float v = 0.f;

    if (q < NTOT) {
        const float2* pts;
        const int* cnt;
        const float* own;
        float delta, scale;
        int k;
        if (q < NP) {
            pts = g_ptsR; cnt = g_cntR; own = pc;
            delta = DELTA_P; scale = 0.5f / (float)NP; k = q;
        } else {
            pts = g_ptsP; cnt = g_cntP; own = ref;
            delta = DELTA_R; scale = 0.5f / (float)NR; k = q - NP;
        }

        int i = (int)((float)k * delta);
        float2 p = *reinterpret_cast<const float2*>(own + 2 * i);
        float px = p.x, py = p.y;
        int cx = clamp_cell((int)(px * (float)GK));
        int cy = clamp_cell((int)(py * (float)GK));

        // my share of the 3x3 neighborhood: cell par; par==0 also takes cell 8
        int cells[2], ms[2], ncl = 0;
        #pragma unroll
        for (int c = par; c < 9; c += 8) {
            int yy = cy + c / 3 - 1;
            int xx = cx + c % 3 - 1;
            if (yy >= 0 && yy < GK && xx >= 0 && xx < GK)
                cells[ncl++] = yy * GK + xx;
        }
        // prefetch counts (independent loads)
        #pragma unroll
        for (int t = 0; t < 2; t++) {
            int m = (t < ncl) ? cnt[cells[t]] : 0;
            ms[t] = m < CAP ? m : CAP;
        }

        float dmin = 1e30f;
        #pragma unroll
        for (int t = 0; t < 2; t++) {
            const float2* basep = pts + cells[t] * CAP;   // 16B-aligned (CAP even)
            int m = ms[t];
            int s = 0;
            for (; s + 2 <= m; s += 2) {                  // 2 points per LDG.128
                float4 pq = *reinterpret_cast<const float4*>(basep + s);
                float dx0 = px - pq.x, dy0 = py - pq.y;
                float dx1 = px - pq.z, dy1 = py - pq.w;
                dmin = fminf(dmin, fmaf(dx0, dx0, dy0 * dy0));
                dmin = fminf(dmin, fmaf(dx1, dx1, dy1 * dy1));
            }
            if (s < m) {
                float2 pp = basep[s];
                float ddx = px - pp.x, ddy = py - pp.y;
                dmin = fminf(dmin, fmaf(ddx, ddx, ddy * ddy));
            }
        }

        // combine the 8 partners (contiguous lanes of one warp)
        dmin = fminf(dmin, __shfl_xor_sync(FULLM, dmin, 1));
        dmin = fminf(dmin, __shfl_xor_sync(FULLM, dmin, 2));
        dmin = fminf(dmin, __shfl_xor_sync(FULLM, dmin, 4));

        if (par == 0) {
            // expanding-ring fallback (rare): after radius-r square, coverage r*CS
            int r = 1;
            float cov = CS;
            while (dmin > cov * cov && r < GK - 1) {
                r++;
                cov = (float)r * CS;
                for (int dy = -r; dy <= r; dy++) {
                    int yy = cy + dy;
                    if (yy < 0 || yy >= GK) continue;
                    int step = (dy == -r || dy == r) ? 1 : 2 * r;
                    for (int xx = cx - r; xx <= cx + r; xx += step) {
                        if (xx < 0 || xx >= GK) continue;
                        scan_cell_g(pts, cnt, yy * GK + xx, px, py, dmin);
                    }
                }
            }
            v = sqrtf(dmin) * scale;
        }
    }

    // ================= phase 3: deterministic reduction ======================
    #pragma unroll
    for (int o = 16; o > 0; o >>= 1)
        v += __shfl_xor_sync(FULLM, v, o);

    __shared__ float sw[TPB / 32];
    int lane = tid & 31, wid = tid >> 5;
    if (lane == 0) sw[wid] = v;
    __syncthreads();

    __shared__ int lastf;
    if (tid == 0) {
        float s = 0.f;
        #pragma unroll
        for (int w = 0; w < TPB / 32; w++) s += sw[w];
        g_part[b] = s;
        __threadfence();
        unsigned int done = atomicAdd(&g_sync2, 1u);
        lastf = (done == NBLK - 1) ? 1 : 0;
    }
    __syncthreads();

    if (lastf) {
        if (tid == 0) __threadfence();
        __syncthreads();

        // fixed per-thread strided order over partials -> deterministic
        float acc = 0.f;
        for (int t = tid; t < NBLK; t += TPB)
            acc += g_part[t];

        #pragma unroll
        for (int o = 16; o > 0; o >>= 1)
            acc += __shfl_xor_sync(FULLM, acc, o);
        if (lane == 0) sw[wid] = acc;
        __syncthreads();

        if (tid == 0) {
            float t = 0.f;
            #pragma unroll
            for (int w = 0; w < TPB / 32; w++) t += sw[w];
            out[0] = t;
            g_sync1 = 0;
            g_sync2 = 0;
        }
        // zero bucket counters for next graph replay (all readers finished)
        for (int c = tid; c < NCELL; c += TPB) {
            g_cntP[c] = 0;
            g_cntR[c] = 0;
        }
    }
}

extern "C" void kernel_launch(void* const* d_in, const int* in_sizes, int n_in,
                              void* d_out, int out_size) {
    const float* pc  = (const float*)d_in[0];   // img_render_points (64000 x 2)
    const float* ref = (const float*)d_in[1];   // ref point cloud   (80000 x 2)

    chamfer_fused<<<NBLK, TPB>>>(pc, ref, (float*)d_out);
}

// round 16
// speedup vs baseline: 1.3709x; 1.3709x over previous
#include <cuda_runtime.h>

// ContourChamferLoss on GB300 (sm_103a) — round 16
// ONE fused kernel: scatter -> software grid barrier -> 4-threads-per-query
// exact NN over quadrant-directed 2x2 cell region (certified by per-query
// coverage radius; expanding-square fallback) -> deterministic reduction.

#define NP_TOT 64000
#define NR_TOT 80000
#define NP     8000
#define NR     10000
#define NTOT   (NP + NR)

// exact f32 replication of jnp.linspace(0, n-1, n//8) index math
#define DELTA_P ((float)(NP_TOT - 1) / (float)(NP - 1))
#define DELTA_R ((float)(NR_TOT - 1) / (float)(NR - 1))

#define GK    32
#define NCELL (GK * GK)
#define CS    (1.0f / (float)GK)
#define CAP   128

#define TPB   128
#define QPB   (TPB / 4)                  // 32 queries per block (4 threads/query)
#define NBLK  ((NTOT + QPB - 1) / QPB)   // 563 blocks (proven co-resident)

#define FULLM 0xFFFFFFFFu

// ---- device scratch (static zero-init; no allocation) ----
// Counters reset by last block each run -> graph replays start clean.
// Bucket slot order may vary, but min is order-independent and partial sums
// are keyed by query index -> bit-stable output.
__device__ int    g_cntP[NCELL];
__device__ int    g_cntR[NCELL];
__device__ float2 g_ptsP[NCELL * CAP];
__device__ float2 g_ptsR[NCELL * CAP];
__device__ float  g_part[NBLK];
__device__ unsigned int g_sync1;         // scatter-done barrier
__device__ unsigned int g_sync2;         // search-done ticket

__device__ __forceinline__ int clamp_cell(int c) {
    return c < 0 ? 0 : (c > GK - 1 ? GK - 1 : c);
}

__device__ __forceinline__ void scan_cell_g(const float2* __restrict__ pts,
                                            const int* __restrict__ cnt,
                                            int c, float px, float py, float& dmin) {
    int m = cnt[c];
    m = m < CAP ? m : CAP;
    const float2* q = pts + c * CAP;
    for (int t = 0; t < m; t++) {
        float2 pp = q[t];
        float ddx = px - pp.x, ddy = py - pp.y;
        dmin = fminf(dmin, fmaf(ddx, ddx, ddy * ddy));
    }
}

__global__ __launch_bounds__(TPB) void chamfer_fused(const float* __restrict__ pc,
                                                     const float* __restrict__ ref,
                                                     float* __restrict__ out) {
    int tid = threadIdx.x;
    int b   = blockIdx.x;

    // ================= phase 1: scatter (first 141 blocks carry points) ======
    int g = b * TPB + tid;
    if (g < NP) {
        int i = (int)((float)g * DELTA_P);
        float2 p = *reinterpret_cast<const float2*>(pc + 2 * i);
        int c = clamp_cell((int)(p.y * (float)GK)) * GK + clamp_cell((int)(p.x * (float)GK));
        int s = atomicAdd(&g_cntP[c], 1);
        if (s < CAP) g_ptsP[c * CAP + s] = p;
    } else if (g < NTOT) {
        int j = g - NP;
        int i = (int)((float)j * DELTA_R);
        float2 p = *reinterpret_cast<const float2*>(ref + 2 * i);
        int c = clamp_cell((int)(p.y * (float)GK)) * GK + clamp_cell((int)(p.x * (float)GK));
        int s = atomicAdd(&g_cntR[c], 1);
        if (s < CAP) g_ptsR[c * CAP + s] = p;
    }

    // ================= software grid barrier (all blocks co-resident) ========
    __syncthreads();
    if (tid == 0) {
        __threadfence();                               // release scatter writes
        atomicAdd(&g_sync1, 1u);
        unsigned int v;
        do {
            asm volatile("ld.acquire.gpu.u32 %0, [%1];"
                         : "=r"(v) : "l"(&g_sync1) : "memory");
            if (v < NBLK) __nanosleep(64);
        } while (v < NBLK);
    }
    __syncthreads();

    // ================= phase 2: search (4 threads/query, 2x2 region) =========
    int q   = (b * TPB + tid) >> 2;
    int par = tid & 3;
    float v = 0.f;

    if (q < NTOT) {
        const float2* pts;
        const int* cnt;
        const float* own;
        float delta, scale;
        int k;
        if (q < NP) {
            pts = g_ptsR; cnt = g_cntR; own = pc;
            delta = DELTA_P; scale = 0.5f / (float)NP; k = q;
        } else {
            pts = g_ptsP; cnt = g_cntP; own = ref;
            delta = DELTA_R; scale = 0.5f / (float)NR; k = q - NP;
        }

        int i = (int)((float)k * delta);
        float2 p = *reinterpret_cast<const float2*>(own + 2 * i);
        float px = p.x, py = p.y;
        int cx = clamp_cell((int)(px * (float)GK));
        int cy = clamp_cell((int)(py * (float)GK));

        // quadrant-directed neighbor direction
        float fx = px * (float)GK - (float)cx;
        float fy = py * (float)GK - (float)cy;
        int sx = fx >= 0.5f ? 1 : -1;
        int sy = fy >= 0.5f ? 1 : -1;
        int nxc = cx + sx;
        int nyc = cy + sy;
        bool hx = (nxc >= 0) && (nxc < GK);
        bool hy = (nyc >= 0) && (nyc < GK);

        // this thread's cell of the 2x2 region: (par&1) selects x-neighbor,
        // (par>>1) selects y-neighbor. Clipped cells -> no work.
        int tx = (par & 1) ? nxc : cx;
        int ty = (par >> 1) ? nyc : cy;
        bool valid = ((par & 1) ? hx : true) && ((par >> 1) ? hy : true);

        int m = 0, base = 0;
        if (valid) {
            int cell = ty * GK + tx;
            base = cell * CAP;
            m = cnt[cell];
            m = m < CAP ? m : CAP;
        }

        float dmin = 1e30f;
        {
            const float2* basep = pts + base;            // 16B-aligned (CAP even)
            int s = 0;
            for (; s + 2 <= m; s += 2) {                 // 2 points per LDG.128
                float4 pq = *reinterpret_cast<const float4*>(basep + s);
                float dx0 = px - pq.x, dy0 = py - pq.y;
                float dx1 = px - pq.z, dy1 = py - pq.w;
                dmin = fminf(dmin, fmaf(dx0, dx0, dy0 * dy0));
                dmin = fminf(dmin, fmaf(dx1, dx1, dy1 * dy1));
            }
            if (s < m) {
                float2 pp = basep[s];
                float ddx = px - pp.x, ddy = py - pp.y;
                dmin = fminf(dmin, fmaf(ddx, ddx, ddy * ddy));
            }
        }

        // combine the 4 partners (contiguous lanes of one warp)
        dmin = fminf(dmin, __shfl_xor_sync(FULLM, dmin, 1));
        dmin = fminf(dmin, __shfl_xor_sync(FULLM, dmin, 2));

        if (par == 0) {
            // coverage radius: distance to nearest INTERIOR region edge.
            // Domain edges (0 / 1) are infinite coverage: all points in [0,1).
            int xloC = hx ? (sx < 0 ? nxc : cx) : cx;
            int xhiC = hx ? (sx > 0 ? nxc : cx) : cx;
            int yloC = hy ? (sy < 0 ? nyc : cy) : cy;
            int yhiC = hy ? (sy > 0 ? nyc : cy) : cy;
            float xL = (float)xloC * CS;
            float xR = (float)(xhiC + 1) * CS;
            float yL = (float)yloC * CS;
            float yR = (float)(yhiC + 1) * CS;
            float cov = 1e30f;
            if (xloC > 0)      cov = fminf(cov, px - xL);
            if (xhiC < GK - 1) cov = fminf(cov, xR - px);
            if (yloC > 0)      cov = fminf(cov, py - yL);
            if (yhiC < GK - 1) cov = fminf(cov, yR - py);

            if (dmin > cov * cov) {
                // fallback: expanding squares from r=1 (full 3x3, then rings).
                // After radius-r square, coverage lower bound is r*CS.
                int r = 0;
                float covr = 0.f;
                while (dmin > covr * covr && r < GK - 1) {
                    r++;
                    covr = (float)r * CS;
                    if (r == 1) {
                        for (int yy = clamp_cell(cy - 1); yy <= clamp_cell(cy + 1); yy++)
                            for (int xx = clamp_cell(cx - 1); xx <= clamp_cell(cx + 1); xx++)
                                scan_cell_g(pts, cnt, yy * GK + xx, px, py, dmin);
                    } else {
                        for (int dy = -r; dy <= r; dy++) {
                            int yy = cy + dy;
                            if (yy < 0 || yy >= GK) continue;
                            int step = (dy == -r || dy == r) ? 1 : 2 * r;
                            for (int xx = cx - r; xx <= cx + r; xx += step) {
                                if (xx < 0 || xx >= GK) continue;
                                scan_cell_g(pts, cnt, yy * GK + xx, px, py, dmin);
                            }
                        }
                    }
                }
            }
            v = sqrtf(dmin) * scale;
        }
    }

    // ================= phase 3: deterministic reduction ======================
    #pragma unroll
    for (int o = 16; o > 0; o >>= 1)
        v += __shfl_xor_sync(FULLM, v, o);

    __shared__ float sw[TPB / 32];
    int lane = tid & 31, wid = tid >> 5;
    if (lane == 0) sw[wid] = v;
    __syncthreads();

    __shared__ int lastf;
    if (tid == 0) {
        float s = 0.f;
        #pragma unroll
        for (int w = 0; w < TPB / 32; w++) s += sw[w];
        g_part[b] = s;
        __threadfence();
        unsigned int done = atomicAdd(&g_sync2, 1u);
        lastf = (done == NBLK - 1) ? 1 : 0;
    }
    __syncthreads();

    if (lastf) {
        if (tid == 0) __threadfence();
        __syncthreads();

        // fixed per-thread strided order over partials -> deterministic
        float acc = 0.f;
        for (int t = tid; t < NBLK; t += TPB)
            acc += g_part[t];

        #pragma unroll
        for (int o = 16; o > 0; o >>= 1)
            acc += __shfl_xor_sync(FULLM, acc, o);
        if (lane == 0) sw[wid] = acc;
        __syncthreads();

        if (tid == 0) {
            float t = 0.f;
            #pragma unroll
            for (int w = 0; w < TPB / 32; w++) t += sw[w];
            out[0] = t;
            g_sync1 = 0;
            g_sync2 = 0;
        }
        // zero bucket counters for next graph replay (all readers finished)
        for (int c = tid; c < NCELL; c += TPB) {
            g_cntP[c] = 0;
            g_cntR[c] = 0;
        }
    }
}

extern "C" void kernel_launch(void* const* d_in, const int* in_sizes, int n_in,
                              void* d_out, int out_size) {
    const float* pc  = (const float*)d_in[0];   // img_render_points (64000 x 2)
    const float* ref = (const float*)d_in[1];   // ref point cloud   (80000 x 2)

    chamfer_fused<<<NBLK, TPB>>>(pc, ref, (float*)d_out);
}